// round 7
// baseline (speedup 1.0000x reference)
#include <cuda_runtime.h>
#include <math.h>

#define N_NODES 20000
#define N_EDGES 100000

typedef unsigned long long ull;

// scratch (static __device__ per harness rules)
// g_node layout per node (512 floats): [s(128) | v0(128) | v1(128) | v2(128)]
static __device__ float g_node[N_NODES * 512];
static __device__ float g_h[N_EDGES * 64];

#define SILU_NORM 1.6790390826f

__device__ __forceinline__ float act(float x) {
    return SILU_NORM * x / (1.0f + __expf(-x));
}

__device__ __forceinline__ ull pk2(float lo, float hi) {
    ull r; asm("mov.b64 %0, {%1,%2};" : "=l"(r) : "f"(lo), "f"(hi)); return r;
}
__device__ __forceinline__ void fma2(ull& d, ull a, ull b) {
    asm("fma.rn.f32x2 %0, %1, %2, %0;" : "+l"(d) : "l"(a), "l"(b));
}
__device__ __forceinline__ ull mul2(ull a, ull b) {
    ull r; asm("mul.rn.f32x2 %0, %1, %2;" : "=l"(r) : "l"(a), "l"(b)); return r;
}
__device__ __forceinline__ float rsum(ull v) {
    float lo, hi; asm("mov.b64 {%0,%1}, %2;" : "=f"(lo), "=f"(hi) : "l"(v));
    return lo + hi;
}

// ---------------------------------------------------------------------------
// Kernel 1: node up-projection (SoA output).
// 256 threads: warp per node (8 nodes/iter), lane cg owns cols 4cg..4cg+3.
// smem fl: sWsP 16384 | sWvP 16384 | snf 4096  = 36864 fl (144 KB)
// ---------------------------------------------------------------------------
__global__ void __launch_bounds__(256) node_kernel(
    const float* __restrict__ nf,
    const float* __restrict__ Wus,
    const float* __restrict__ Wuv)
{
    extern __shared__ float sm[];
    ull* sWsP = (ull*)sm;             // 8192 ull
    ull* sWvP = (ull*)(sm + 16384);   // 8192 ull
    float* snf = sm + 32768;          // 8 nodes * 512
    int t = threadIdx.x;

    // stage pair-interleaved weights: [u2*128 + c] = {W[2u2][c], W[2u2+1][c]}
    for (int i = t; i < 8192; i += 256) {
        int u2 = i >> 7, c = i & 127;
        sWsP[i] = pk2(Wus[(2 * u2) * 128 + c], Wus[(2 * u2 + 1) * 128 + c]);
        sWvP[i] = pk2(Wuv[(2 * u2) * 128 + c], Wuv[(2 * u2 + 1) * 128 + c]);
    }
    __syncthreads();

    int warp = t >> 5, cg = t & 31;
    const float inv = 0.08838834764831845f; // 1/sqrt(128)

    for (int base = blockIdx.x * 8; base < N_NODES; base += gridDim.x * 8) {
        // stage 8 node rows, de-interleaving v: snf[nd][128 + 128*i + u]
        for (int i = t; i < 4096; i += 256) {
            int nd = i >> 9, ch = i & 511;
            int n = base + nd;
            float v = (n < N_NODES) ? nf[(size_t)n * 512 + ch] : 0.f;
            int pos;
            if (ch < 128) pos = ch;
            else { int j = ch - 128; pos = 128 + (j % 3) * 128 + j / 3; }
            snf[nd * 512 + pos] = v;
        }
        __syncthreads();

        int n = base + warp;
        if (n < N_NODES) {
            const float* row = snf + warp * 512;
            const ull* xs2 = (const ull*)row;
            const ull* x02 = (const ull*)(row + 128);
            const ull* x12 = (const ull*)(row + 256);
            const ull* x22 = (const ull*)(row + 384);
            ull as[4] = {0,0,0,0}, a0[4] = {0,0,0,0}, a1[4] = {0,0,0,0}, a2[4] = {0,0,0,0};
            #pragma unroll 4
            for (int u2 = 0; u2 < 64; ++u2) {
                ull vs = xs2[u2], v0 = x02[u2], v1 = x12[u2], v2 = x22[u2];
                ulonglong2 bsA = *(const ulonglong2*)(sWsP + u2 * 128 + 4 * cg);
                ulonglong2 bsB = *(const ulonglong2*)(sWsP + u2 * 128 + 4 * cg + 2);
                ulonglong2 bvA = *(const ulonglong2*)(sWvP + u2 * 128 + 4 * cg);
                ulonglong2 bvB = *(const ulonglong2*)(sWvP + u2 * 128 + 4 * cg + 2);
                fma2(as[0], vs, bsA.x); fma2(as[1], vs, bsA.y);
                fma2(as[2], vs, bsB.x); fma2(as[3], vs, bsB.y);
                fma2(a0[0], v0, bvA.x); fma2(a0[1], v0, bvA.y);
                fma2(a0[2], v0, bvB.x); fma2(a0[3], v0, bvB.y);
                fma2(a1[0], v1, bvA.x); fma2(a1[1], v1, bvA.y);
                fma2(a1[2], v1, bvB.x); fma2(a1[3], v1, bvB.y);
                fma2(a2[0], v2, bvA.x); fma2(a2[1], v2, bvA.y);
                fma2(a2[2], v2, bvB.x); fma2(a2[3], v2, bvB.y);
            }
            float* o = g_node + (size_t)n * 512;
            float4 r;
            r.x = rsum(as[0]) * inv; r.y = rsum(as[1]) * inv; r.z = rsum(as[2]) * inv; r.w = rsum(as[3]) * inv;
            ((float4*)o)[cg] = r;
            r.x = rsum(a0[0]) * inv; r.y = rsum(a0[1]) * inv; r.z = rsum(a0[2]) * inv; r.w = rsum(a0[3]) * inv;
            ((float4*)(o + 128))[cg] = r;
            r.x = rsum(a1[0]) * inv; r.y = rsum(a1[1]) * inv; r.z = rsum(a1[2]) * inv; r.w = rsum(a1[3]) * inv;
            ((float4*)(o + 256))[cg] = r;
            r.x = rsum(a2[0]) * inv; r.y = rsum(a2[1]) * inv; r.z = rsum(a2[2]) * inv; r.w = rsum(a2[3]) * inv;
            ((float4*)(o + 384))[cg] = r;
        }
        __syncthreads();
    }
}

// ---------------------------------------------------------------------------
// Kernel 2: edge MLP layers 0..2 -> g_h.  128 edges/CTA, 256 threads.
// thread = (es 0..31 owning edges es+32k, dg 0..7 owning dims 8dg..8dg+7)
// smem fl: sw0P 512 | sw1P 4096 | sw2P 4096 | sef 1280 | hA 8448 | hB 8448
// total 26880 fl (105 KB) -> 2 CTAs/SM
// ---------------------------------------------------------------------------
__global__ void __launch_bounds__(256) mlp_kernel(
    const float* __restrict__ ef,
    const float* __restrict__ w0,
    const float* __restrict__ w1,
    const float* __restrict__ w2)
{
    extern __shared__ float sm[];
    ull*  sw0P = (ull*)sm;              // 256 ull
    ull*  sw1P = (ull*)(sm + 512);      // 2048 ull
    ull*  sw2P = (ull*)(sm + 4608);     // 2048 ull
    float* sef = sm + 8704;             // 128*10
    float* hA  = sm + 9984;             // 128*66
    float* hB  = sm + 18432;            // 128*66

    int t = threadIdx.x;
    const float is8 = 0.35355339059327373f;
    for (int i = t; i < 256; i += 256) {
        int u2 = i >> 6, d = i & 63;
        sw0P[i] = pk2(w0[(2 * u2) * 64 + d] * is8, w0[(2 * u2 + 1) * 64 + d] * is8);
    }
    for (int i = t; i < 2048; i += 256) {
        int u2 = i >> 6, d = i & 63;
        sw1P[i] = pk2(w1[(2 * u2) * 64 + d] * 0.125f, w1[(2 * u2 + 1) * 64 + d] * 0.125f);
        sw2P[i] = pk2(w2[(2 * u2) * 64 + d] * 0.125f, w2[(2 * u2 + 1) * 64 + d] * 0.125f);
    }
    int ebase = blockIdx.x * 128;
    int nvalid = N_EDGES - ebase; if (nvalid > 128) nvalid = 128;
    for (int i = t; i < 1024; i += 256) {
        int e = i >> 3, u = i & 7;
        sef[e * 10 + u] = (e < nvalid) ? ef[(size_t)(ebase + e) * 8 + u] : 0.f;
    }
    __syncthreads();

    int es = t & 31;
    int dg = t >> 5;
    ull acc[4][8];

    // ---- layer 0 (K=8) ----
    #pragma unroll
    for (int k = 0; k < 4; ++k)
        #pragma unroll
        for (int d = 0; d < 8; ++d) acc[k][d] = 0;
    #pragma unroll
    for (int u2 = 0; u2 < 4; ++u2) {
        ull a0 = ((const ull*)sef)[(es)      * 5 + u2];
        ull a1 = ((const ull*)sef)[(es + 32) * 5 + u2];
        ull a2 = ((const ull*)sef)[(es + 64) * 5 + u2];
        ull a3 = ((const ull*)sef)[(es + 96) * 5 + u2];
        #pragma unroll
        for (int dp = 0; dp < 4; ++dp) {
            ulonglong2 b = *(const ulonglong2*)(sw0P + u2 * 64 + 8 * dg + 2 * dp);
            fma2(acc[0][2*dp], a0, b.x); fma2(acc[0][2*dp+1], a0, b.y);
            fma2(acc[1][2*dp], a1, b.x); fma2(acc[1][2*dp+1], a1, b.y);
            fma2(acc[2][2*dp], a2, b.x); fma2(acc[2][2*dp+1], a2, b.y);
            fma2(acc[3][2*dp], a3, b.x); fma2(acc[3][2*dp+1], a3, b.y);
        }
    }
    #pragma unroll
    for (int k = 0; k < 4; ++k)
        #pragma unroll
        for (int d = 0; d < 8; ++d)
            hA[(es + 32 * k) * 66 + 8 * dg + d] = act(rsum(acc[k][d]));
    __syncthreads();

    // ---- layer 1 (K=64) ----
    #pragma unroll
    for (int k = 0; k < 4; ++k)
        #pragma unroll
        for (int d = 0; d < 8; ++d) acc[k][d] = 0;
    #pragma unroll 4
    for (int u2 = 0; u2 < 32; ++u2) {
        ull a0 = ((const ull*)hA)[(es)      * 33 + u2];
        ull a1 = ((const ull*)hA)[(es + 32) * 33 + u2];
        ull a2 = ((const ull*)hA)[(es + 64) * 33 + u2];
        ull a3 = ((const ull*)hA)[(es + 96) * 33 + u2];
        #pragma unroll
        for (int dp = 0; dp < 4; ++dp) {
            ulonglong2 b = *(const ulonglong2*)(sw1P + u2 * 64 + 8 * dg + 2 * dp);
            fma2(acc[0][2*dp], a0, b.x); fma2(acc[0][2*dp+1], a0, b.y);
            fma2(acc[1][2*dp], a1, b.x); fma2(acc[1][2*dp+1], a1, b.y);
            fma2(acc[2][2*dp], a2, b.x); fma2(acc[2][2*dp+1], a2, b.y);
            fma2(acc[3][2*dp], a3, b.x); fma2(acc[3][2*dp+1], a3, b.y);
        }
    }
    #pragma unroll
    for (int k = 0; k < 4; ++k)
        #pragma unroll
        for (int d = 0; d < 8; ++d)
            hB[(es + 32 * k) * 66 + 8 * dg + d] = act(rsum(acc[k][d]));
    __syncthreads();

    // ---- layer 2 (K=64) -> hA ----
    #pragma unroll
    for (int k = 0; k < 4; ++k)
        #pragma unroll
        for (int d = 0; d < 8; ++d) acc[k][d] = 0;
    #pragma unroll 4
    for (int u2 = 0; u2 < 32; ++u2) {
        ull a0 = ((const ull*)hB)[(es)      * 33 + u2];
        ull a1 = ((const ull*)hB)[(es + 32) * 33 + u2];
        ull a2 = ((const ull*)hB)[(es + 64) * 33 + u2];
        ull a3 = ((const ull*)hB)[(es + 96) * 33 + u2];
        #pragma unroll
        for (int dp = 0; dp < 4; ++dp) {
            ulonglong2 b = *(const ulonglong2*)(sw2P + u2 * 64 + 8 * dg + 2 * dp);
            fma2(acc[0][2*dp], a0, b.x); fma2(acc[0][2*dp+1], a0, b.y);
            fma2(acc[1][2*dp], a1, b.x); fma2(acc[1][2*dp+1], a1, b.y);
            fma2(acc[2][2*dp], a2, b.x); fma2(acc[2][2*dp+1], a2, b.y);
            fma2(acc[3][2*dp], a3, b.x); fma2(acc[3][2*dp+1], a3, b.y);
        }
    }
    #pragma unroll
    for (int k = 0; k < 4; ++k)
        #pragma unroll
        for (int d = 0; d < 8; ++d)
            hA[(es + 32 * k) * 66 + 8 * dg + d] = act(rsum(acc[k][d]));
    __syncthreads();

    // coalesced write-back via ull
    for (int i = t; i < 4096; i += 256) {
        int el = i >> 5, off = i & 31;
        if (ebase + el < N_EDGES)
            ((ull*)g_h)[(size_t)(ebase + el) * 32 + off] = ((const ull*)hA)[el * 33 + off];
    }
}

// ---------------------------------------------------------------------------
// Kernel 3: fused tpw + tensor product + output GEMMs.
// 32 edges/CTA, 512 threads: warp w owns edges 2w..2w+1, lane cg cols 4cg..4cg+3
// smem fl: ssv 16384 | sA 8192 | sP 4096 | sQ 4096 | sh 2048 | sWp 16384 | sea 128 | snd 32
// total 51360 fl (200.6 KB)
// ---------------------------------------------------------------------------
__device__ __forceinline__ void stage64(ull* dst, const float* __restrict__ src,
                                        int row0, int rowStride, int col0, int t) {
    #pragma unroll
    for (int j = 0; j < 8; ++j) {
        int i = t + 512 * j;                 // < 4096
        int u2 = i >> 7, c = i & 127;
        const float* p = src + (size_t)(row0 + 2 * u2) * rowStride + col0 + c;
        dst[i] = pk2(p[0], p[rowStride]);
    }
}
__device__ __forceinline__ void stage128(ull* dst, const float* __restrict__ src,
                                         int row0, int rowStride, int t) {
    #pragma unroll
    for (int j = 0; j < 16; ++j) {
        int i = t + 512 * j;                 // < 8192
        int u2 = i >> 7, c = i & 127;
        const float* p = src + (size_t)(row0 + 2 * u2) * rowStride + c;
        dst[i] = pk2(p[0], p[rowStride]);
    }
}

__global__ void __launch_bounds__(512) edge_kernel(
    const float* __restrict__ ea,     // edge_attrs (E,4)
    const int*   __restrict__ eidx,   // edge_index (2,E): sender first
    const float* __restrict__ w3,     // (64,512)
    const float* __restrict__ Wos,    // (256,128)
    const float* __restrict__ Wov,    // (256,128)
    float* __restrict__ out)
{
    extern __shared__ float sm[];
    float* ssv = sm;                  // 32*512 SoA [s|v0|v1|v2]
    float* sA  = sm + 16384;          // 32*256
    float* sP  = sm + 24576;          // 32*128
    float* sQ  = sm + 28672;          // 32*128
    float* sh  = sm + 32768;          // 32*64
    ull*   sWp = (ull*)(sm + 34816);  // 8192 ull
    float* sea = sm + 51200;          // 128
    int*   snd = (int*)(sm + 51328);  // 32

    const float C0 = 0.70710678118654752f / 128.0f;
    const float C3 = 0.70710678118654752f / (128.0f * 1.7320508075688772f);

    int t = threadIdx.x;
    int warp = t >> 5;
    int cg = t & 31;
    int ebase = blockIdx.x * 32;
    int e0 = warp * 2;

    if (t < 32) snd[t] = eidx[ebase + t];
    if (t >= 64 && t < 192) sea[t - 64] = ea[ebase * 4 + (t - 64)];
    __syncthreads();

    { // gather node rows (32 x 128 float4, 16 threads/row)
        int r = t >> 4, q = t & 15;
        const float4* src = (const float4*)g_node + (size_t)snd[r] * 128;
        float4* dst = (float4*)ssv + r * 128;
        #pragma unroll
        for (int j = 0; j < 8; ++j) dst[q + 16 * j] = src[q + 16 * j];
    }
    // h tile (512 float4)
    ((float4*)sh)[t] = ((const float4*)g_h)[(size_t)ebase * 16 + t];

    // ---- tpw chunks -> A / P / Q (coefficients folded) ----
    const ull* h0 = (const ull*)(sh + e0 * 64);
    const ull* h1 = (const ull*)(sh + (e0 + 1) * 64);
    for (int c = 0; c < 4; ++c) {
        __syncthreads();
        stage64(sWp, w3, 0, 512, 128 * c, t);
        __syncthreads();

        ull acc[2][4] = {{0,0,0,0},{0,0,0,0}};
        #pragma unroll 4
        for (int u2 = 0; u2 < 32; ++u2) {
            ull a0 = h0[u2], a1 = h1[u2];
            ulonglong2 bA = *(const ulonglong2*)(sWp + u2 * 128 + 4 * cg);
            ulonglong2 bB = *(const ulonglong2*)(sWp + u2 * 128 + 4 * cg + 2);
            fma2(acc[0][0], a0, bA.x); fma2(acc[0][1], a0, bA.y);
            fma2(acc[0][2], a0, bB.x); fma2(acc[0][3], a0, bB.y);
            fma2(acc[1][0], a1, bA.x); fma2(acc[1][1], a1, bA.y);
            fma2(acc[1][2], a1, bB.x); fma2(acc[1][3], a1, bB.y);
        }
        #pragma unroll
        for (int k = 0; k < 2; ++k) {
            int e = e0 + k;
            float r0 = rsum(acc[k][0]), r1 = rsum(acc[k][1]);
            float r2 = rsum(acc[k][2]), r3 = rsum(acc[k][3]);
            float s0 = sea[e * 4];
            if (c == 0) {
                float4 sv = ((const float4*)(ssv + e * 512))[cg];
                ((float4*)sA)[e * 64 + cg] = make_float4(
                    C0 * r0 * sv.x * s0, C0 * r1 * sv.y * s0,
                    C0 * r2 * sv.z * s0, C0 * r3 * sv.w * s0);
            } else if (c == 1) {
                float4 sv = ((const float4*)(ssv + e * 512))[cg];
                ((float4*)sP)[e * 32 + cg] = make_float4(
                    C0 * r0 * sv.x, C0 * r1 * sv.y, C0 * r2 * sv.z, C0 * r3 * sv.w);
            } else if (c == 2) {
                ((float4*)sQ)[e * 32 + cg] = make_float4(
                    C0 * r0 * s0, C0 * r1 * s0, C0 * r2 * s0, C0 * r3 * s0);
            } else {
                float s1 = sea[e * 4 + 1], s2 = sea[e * 4 + 2], s3 = sea[e * 4 + 3];
                float4 v0 = ((const float4*)(ssv + e * 512 + 128))[cg];
                float4 v1 = ((const float4*)(ssv + e * 512 + 256))[cg];
                float4 v2 = ((const float4*)(ssv + e * 512 + 384))[cg];
                ((float4*)sA)[e * 64 + 32 + cg] = make_float4(
                    C3 * r0 * (v0.x * s1 + v1.x * s2 + v2.x * s3),
                    C3 * r1 * (v0.y * s1 + v1.y * s2 + v2.y * s3),
                    C3 * r2 * (v0.z * s1 + v1.z * s2 + v2.z * s3),
                    C3 * r3 * (v0.w * s1 + v1.w * s2 + v2.w * s3));
            }
        }
    }

    // ---- out_s = A(32x256) @ Wos ----
    {
        ull accs[2][4] = {{0,0,0,0},{0,0,0,0}};
        const ull* A0 = (const ull*)(sA + e0 * 256);
        const ull* A1 = (const ull*)(sA + (e0 + 1) * 256);
        for (int kt = 0; kt < 2; ++kt) {
            __syncthreads();
            stage128(sWp, Wos, kt * 128, 128, t);
            __syncthreads();
            #pragma unroll 4
            for (int u2 = 0; u2 < 64; ++u2) {
                ull a0 = A0[kt * 64 + u2], a1 = A1[kt * 64 + u2];
                ulonglong2 bA = *(const ulonglong2*)(sWp + u2 * 128 + 4 * cg);
                ulonglong2 bB = *(const ulonglong2*)(sWp + u2 * 128 + 4 * cg + 2);
                fma2(accs[0][0], a0, bA.x); fma2(accs[0][1], a0, bA.y);
                fma2(accs[0][2], a0, bB.x); fma2(accs[0][3], a0, bB.y);
                fma2(accs[1][0], a1, bA.x); fma2(accs[1][1], a1, bA.y);
                fma2(accs[1][2], a1, bB.x); fma2(accs[1][3], a1, bB.y);
            }
        }
        #pragma unroll
        for (int k = 0; k < 2; ++k) {
            size_t e = (size_t)(ebase + e0 + k);
            ((float4*)out)[e * 128 + cg] = make_float4(
                rsum(accs[k][0]), rsum(accs[k][1]), rsum(accs[k][2]), rsum(accs[k][3]));
        }
    }

    // ---- Q part: QV_i = (Q*vs_i) @ Wv_bot (single pass K=128) ----
    float qv[3][2][4];
    {
        ull accq[3][2][4];
        #pragma unroll
        for (int i = 0; i < 3; ++i)
            #pragma unroll
            for (int k = 0; k < 2; ++k)
                #pragma unroll
                for (int j = 0; j < 4; ++j) accq[i][k][j] = 0;
        __syncthreads();
        stage128(sWp, Wov, 128, 128, t);
        __syncthreads();
        const ull* Q0 = (const ull*)(sQ + e0 * 128);
        const ull* Q1 = (const ull*)(sQ + (e0 + 1) * 128);
        const ull* V00 = (const ull*)(ssv + e0 * 512 + 128);
        const ull* V01 = (const ull*)(ssv + e0 * 512 + 256);
        const ull* V02 = (const ull*)(ssv + e0 * 512 + 384);
        const ull* V10 = (const ull*)(ssv + (e0 + 1) * 512 + 128);
        const ull* V11 = (const ull*)(ssv + (e0 + 1) * 512 + 256);
        const ull* V12 = (const ull*)(ssv + (e0 + 1) * 512 + 384);
        #pragma unroll 2
        for (int u2 = 0; u2 < 64; ++u2) {
            ulonglong2 bA = *(const ulonglong2*)(sWp + u2 * 128 + 4 * cg);
            ulonglong2 bB = *(const ulonglong2*)(sWp + u2 * 128 + 4 * cg + 2);
            {
                ull q = Q0[u2];
                ull p0 = mul2(q, V00[u2]), p1 = mul2(q, V01[u2]), p2 = mul2(q, V02[u2]);
                fma2(accq[0][0][0], p0, bA.x); fma2(accq[0][0][1], p0, bA.y);
                fma2(accq[0][0][2], p0, bB.x); fma2(accq[0][0][3], p0, bB.y);
                fma2(accq[1][0][0], p1, bA.x); fma2(accq[1][0][1], p1, bA.y);
                fma2(accq[1][0][2], p1, bB.x); fma2(accq[1][0][3], p1, bB.y);
                fma2(accq[2][0][0], p2, bA.x); fma2(accq[2][0][1], p2, bA.y);
                fma2(accq[2][0][2], p2, bB.x); fma2(accq[2][0][3], p2, bB.y);
            }
            {
                ull q = Q1[u2];
                ull p0 = mul2(q, V10[u2]), p1 = mul2(q, V11[u2]), p2 = mul2(q, V12[u2]);
                fma2(accq[0][1][0], p0, bA.x); fma2(accq[0][1][1], p0, bA.y);
                fma2(accq[0][1][2], p0, bB.x); fma2(accq[0][1][3], p0, bB.y);
                fma2(accq[1][1][0], p1, bA.x); fma2(accq[1][1][1], p1, bA.y);
                fma2(accq[1][1][2], p1, bB.x); fma2(accq[1][1][3], p1, bB.y);
                fma2(accq[2][1][0], p2, bA.x); fma2(accq[2][1][1], p2, bA.y);
                fma2(accq[2][1][2], p2, bB.x); fma2(accq[2][1][3], p2, bB.y);
            }
        }
        #pragma unroll
        for (int i = 0; i < 3; ++i)
            #pragma unroll
            for (int k = 0; k < 2; ++k)
                #pragma unroll
                for (int j = 0; j < 4; ++j) qv[i][k][j] = rsum(accq[i][k][j]);
    }

    // ---- PV = P(32x128) @ Wv_top (single pass K=128) ----
    float pv[2][4];
    {
        ull accp[2][4] = {{0,0,0,0},{0,0,0,0}};
        __syncthreads();
        stage128(sWp, Wov, 0, 128, t);
        __syncthreads();
        const ull* P0 = (const ull*)(sP + e0 * 128);
        const ull* P1 = (const ull*)(sP + (e0 + 1) * 128);
        #pragma unroll 4
        for (int u2 = 0; u2 < 64; ++u2) {
            ull a0 = P0[u2], a1 = P1[u2];
            ulonglong2 bA = *(const ulonglong2*)(sWp + u2 * 128 + 4 * cg);
            ulonglong2 bB = *(const ulonglong2*)(sWp + u2 * 128 + 4 * cg + 2);
            fma2(accp[0][0], a0, bA.x); fma2(accp[0][1], a0, bA.y);
            fma2(accp[0][2], a0, bB.x); fma2(accp[0][3], a0, bB.y);
            fma2(accp[1][0], a1, bA.x); fma2(accp[1][1], a1, bA.y);
            fma2(accp[1][2], a1, bB.x); fma2(accp[1][3], a1, bB.y);
        }
        #pragma unroll
        for (int k = 0; k < 2; ++k)
            #pragma unroll
            for (int j = 0; j < 4; ++j) pv[k][j] = rsum(accp[k][j]);
    }

    // ---- combine + restage out_v through smem for coalesced stores ----
    float* vbuf = sA;   // sA(8192)+sP(4096) contiguous = 12288 fl = 32*384
    __syncthreads();    // all reads of sA/sP done
    #pragma unroll
    for (int k = 0; k < 2; ++k) {
        int e = e0 + k;
        float s1 = sea[e * 4 + 1], s2 = sea[e * 4 + 2], s3 = sea[e * 4 + 3];
        #pragma unroll
        for (int j = 0; j < 4; ++j) {
            int n = cg * 4 + j;
            float p = pv[k][j];
            vbuf[e * 384 + n * 3 + 0] = s1 * p + qv[0][k][j];
            vbuf[e * 384 + n * 3 + 1] = s2 * p + qv[1][k][j];
            vbuf[e * 384 + n * 3 + 2] = s3 * p + qv[2][k][j];
        }
    }
    __syncthreads();
    float4* vb4 = (float4*)vbuf;
    #pragma unroll
    for (int j = 0; j < 6; ++j) {
        int idx = t + 512 * j;      // < 3072
        int e = idx / 96, rem = idx % 96;
        ((float4*)out)[(size_t)(ebase + e) * 128 + 32 + rem] = vb4[idx];
    }
}

// ---------------------------------------------------------------------------
extern "C" void kernel_launch(void* const* d_in, const int* in_sizes, int n_in,
                              void* d_out, int out_size) {
    const float* node_feats = (const float*)d_in[0];
    const float* edge_attrs = (const float*)d_in[1];
    const float* edge_feats = (const float*)d_in[2];
    const int*   edge_index = (const int*)d_in[3];
    const float* W_up_s  = (const float*)d_in[4];
    const float* W_up_v  = (const float*)d_in[5];
    const float* mlp_w0  = (const float*)d_in[6];
    const float* mlp_w1  = (const float*)d_in[7];
    const float* mlp_w2  = (const float*)d_in[8];
    const float* mlp_w3  = (const float*)d_in[9];
    const float* W_out_s = (const float*)d_in[10];
    const float* W_out_v = (const float*)d_in[11];
    float* out = (float*)d_out;

    size_t smem1 = (size_t)36864 * 4;   // 144 KB
    size_t smem2 = (size_t)26880 * 4;   // 105 KB
    size_t smem3 = (size_t)51360 * 4;   // 200.6 KB
    cudaFuncSetAttribute(node_kernel, cudaFuncAttributeMaxDynamicSharedMemorySize, (int)smem1);
    cudaFuncSetAttribute(mlp_kernel,  cudaFuncAttributeMaxDynamicSharedMemorySize, (int)smem2);
    cudaFuncSetAttribute(edge_kernel, cudaFuncAttributeMaxDynamicSharedMemorySize, (int)smem3);

    node_kernel<<<148, 256, smem1>>>(node_feats, W_up_s, W_up_v);
    mlp_kernel<<<(N_EDGES + 127) / 128, 256, smem2>>>(edge_feats, mlp_w0, mlp_w1, mlp_w2);
    edge_kernel<<<N_EDGES / 32, 512, smem3>>>(edge_attrs, edge_index, mlp_w3,
                                              W_out_s, W_out_v, out);
}

// round 8
// speedup vs baseline: 1.3081x; 1.3081x over previous
#include <cuda_runtime.h>
#include <math.h>

#define N_NODES 20000
#define N_EDGES 100000

typedef unsigned long long ull;

// scratch (static __device__ per harness rules)
// g_node layout per node (512 floats): [s(128) | v0(128) | v1(128) | v2(128)]
static __device__ float g_node[N_NODES * 512];
static __device__ float g_h[N_EDGES * 64];

#define SILU_NORM 1.6790390826f

__device__ __forceinline__ float act(float x) {
    return SILU_NORM * x / (1.0f + __expf(-x));
}

__device__ __forceinline__ ull pk2(float lo, float hi) {
    ull r; asm("mov.b64 %0, {%1,%2};" : "=l"(r) : "f"(lo), "f"(hi)); return r;
}
__device__ __forceinline__ void fma2(ull& d, ull a, ull b) {
    asm("fma.rn.f32x2 %0, %1, %2, %0;" : "+l"(d) : "l"(a), "l"(b));
}
__device__ __forceinline__ float rsum(ull v) {
    float lo, hi; asm("mov.b64 {%0,%1}, %2;" : "=f"(lo), "=f"(hi) : "l"(v));
    return lo + hi;
}

// ---------------------------------------------------------------------------
// Kernel 1: node up-projection (SoA output), f32x2 inner product.
// 512 threads / 16 warps: warp per node (16 nodes/iter), lane owns cols 4cg..4cg+3.
// smem fl: sWsP 16384 | sWvP 16384 | snf 8192 = 40960 fl (160 KB)
// ---------------------------------------------------------------------------
__global__ void __launch_bounds__(512) node_kernel(
    const float* __restrict__ nf,
    const float* __restrict__ Wus,
    const float* __restrict__ Wuv)
{
    extern __shared__ float sm[];
    ull* sWsP = (ull*)sm;             // 8192 ull
    ull* sWvP = (ull*)(sm + 16384);   // 8192 ull
    float* snf = sm + 32768;          // 16 nodes * 512
    int t = threadIdx.x;

    // stage pair-interleaved weights: [u2*128 + c] = {W[2u2][c], W[2u2+1][c]}
    for (int i = t; i < 8192; i += 512) {
        int u2 = i >> 7, c = i & 127;
        sWsP[i] = pk2(Wus[(2 * u2) * 128 + c], Wus[(2 * u2 + 1) * 128 + c]);
        sWvP[i] = pk2(Wuv[(2 * u2) * 128 + c], Wuv[(2 * u2 + 1) * 128 + c]);
    }
    __syncthreads();

    int warp = t >> 5, cg = t & 31;
    const float inv = 0.08838834764831845f; // 1/sqrt(128)

    for (int base = blockIdx.x * 16; base < N_NODES; base += gridDim.x * 16) {
        // stage 16 node rows, de-interleaving v: snf[nd][128 + 128*i + u]
        for (int i = t; i < 8192; i += 512) {
            int nd = i >> 9, ch = i & 511;
            int n = base + nd;
            float v = (n < N_NODES) ? nf[(size_t)n * 512 + ch] : 0.f;
            int pos;
            if (ch < 128) pos = ch;
            else { int j = ch - 128; pos = 128 + (j % 3) * 128 + j / 3; }
            snf[nd * 512 + pos] = v;
        }
        __syncthreads();

        int n = base + warp;
        if (n < N_NODES) {
            const float* row = snf + warp * 512;
            const ull* xs2 = (const ull*)row;
            const ull* x02 = (const ull*)(row + 128);
            const ull* x12 = (const ull*)(row + 256);
            const ull* x22 = (const ull*)(row + 384);
            ull as[4] = {0,0,0,0}, a0[4] = {0,0,0,0}, a1[4] = {0,0,0,0}, a2[4] = {0,0,0,0};
            #pragma unroll 4
            for (int u2 = 0; u2 < 64; ++u2) {
                ull vs = xs2[u2], v0 = x02[u2], v1 = x12[u2], v2 = x22[u2];
                ulonglong2 bsA = *(const ulonglong2*)(sWsP + u2 * 128 + 4 * cg);
                ulonglong2 bsB = *(const ulonglong2*)(sWsP + u2 * 128 + 4 * cg + 2);
                ulonglong2 bvA = *(const ulonglong2*)(sWvP + u2 * 128 + 4 * cg);
                ulonglong2 bvB = *(const ulonglong2*)(sWvP + u2 * 128 + 4 * cg + 2);
                fma2(as[0], vs, bsA.x); fma2(as[1], vs, bsA.y);
                fma2(as[2], vs, bsB.x); fma2(as[3], vs, bsB.y);
                fma2(a0[0], v0, bvA.x); fma2(a0[1], v0, bvA.y);
                fma2(a0[2], v0, bvB.x); fma2(a0[3], v0, bvB.y);
                fma2(a1[0], v1, bvA.x); fma2(a1[1], v1, bvA.y);
                fma2(a1[2], v1, bvB.x); fma2(a1[3], v1, bvB.y);
                fma2(a2[0], v2, bvA.x); fma2(a2[1], v2, bvA.y);
                fma2(a2[2], v2, bvB.x); fma2(a2[3], v2, bvB.y);
            }
            float* o = g_node + (size_t)n * 512;
            float4 r;
            r.x = rsum(as[0]) * inv; r.y = rsum(as[1]) * inv; r.z = rsum(as[2]) * inv; r.w = rsum(as[3]) * inv;
            ((float4*)o)[cg] = r;
            r.x = rsum(a0[0]) * inv; r.y = rsum(a0[1]) * inv; r.z = rsum(a0[2]) * inv; r.w = rsum(a0[3]) * inv;
            ((float4*)(o + 128))[cg] = r;
            r.x = rsum(a1[0]) * inv; r.y = rsum(a1[1]) * inv; r.z = rsum(a1[2]) * inv; r.w = rsum(a1[3]) * inv;
            ((float4*)(o + 256))[cg] = r;
            r.x = rsum(a2[0]) * inv; r.y = rsum(a2[1]) * inv; r.z = rsum(a2[2]) * inv; r.w = rsum(a2[3]) * inv;
            ((float4*)(o + 384))[cg] = r;
        }
        __syncthreads();
    }
}

// ---------------------------------------------------------------------------
// Kernel 2: edge MLP layers 0..2 -> g_h.  128 edges/CTA, 128 threads. (R3 proven)
// ---------------------------------------------------------------------------
__global__ void __launch_bounds__(128) mlp_kernel(
    const float* __restrict__ ef,
    const float* __restrict__ w0,
    const float* __restrict__ w1,
    const float* __restrict__ w2)
{
    extern __shared__ float sm[];
    float* sw0 = sm;              // 512
    float* sw1 = sw0 + 512;       // 4096
    float* sw2 = sw1 + 4096;      // 4096
    float* sef = sw2 + 4096;      // 1024
    float* hA  = sef + 1024;      // 128*65
    float* hB  = hA + 128 * 65;   // 128*65

    int t = threadIdx.x;
    const float is8 = 0.35355339059327373f; // 1/sqrt(8)
    for (int i = t; i < 512; i += 128) sw0[i] = w0[i] * is8;
    for (int i = t; i < 4096; i += 128) { sw1[i] = w1[i] * 0.125f; sw2[i] = w2[i] * 0.125f; }
    int ebase = blockIdx.x * 128;
    int nvalid = N_EDGES - ebase; if (nvalid > 128) nvalid = 128;
    for (int i = t; i < 1024; i += 128)
        sef[i] = (i < nvalid * 8) ? ef[ebase * 8 + i] : 0.f;
    __syncthreads();

    int es = t & 31;
    int dg = t >> 5;
    float acc[4][16];

    // layer 0
    #pragma unroll
    for (int k = 0; k < 4; ++k)
        #pragma unroll
        for (int d = 0; d < 16; ++d) acc[k][d] = 0.f;
    #pragma unroll
    for (int u = 0; u < 8; ++u) {
        float x0 = sef[(es      ) * 8 + u];
        float x1 = sef[(es + 32) * 8 + u];
        float x2 = sef[(es + 64) * 8 + u];
        float x3 = sef[(es + 96) * 8 + u];
        #pragma unroll
        for (int d = 0; d < 16; ++d) {
            float w = sw0[u * 64 + dg * 16 + d];
            acc[0][d] += x0 * w; acc[1][d] += x1 * w; acc[2][d] += x2 * w; acc[3][d] += x3 * w;
        }
    }
    #pragma unroll
    for (int k = 0; k < 4; ++k)
        #pragma unroll
        for (int d = 0; d < 16; ++d)
            hA[(es + 32 * k) * 65 + dg * 16 + d] = act(acc[k][d]);
    __syncthreads();

    // layer 1
    #pragma unroll
    for (int k = 0; k < 4; ++k)
        #pragma unroll
        for (int d = 0; d < 16; ++d) acc[k][d] = 0.f;
    #pragma unroll 8
    for (int u = 0; u < 64; ++u) {
        float x0 = hA[(es      ) * 65 + u];
        float x1 = hA[(es + 32) * 65 + u];
        float x2 = hA[(es + 64) * 65 + u];
        float x3 = hA[(es + 96) * 65 + u];
        #pragma unroll
        for (int d = 0; d < 16; ++d) {
            float w = sw1[u * 64 + dg * 16 + d];
            acc[0][d] += x0 * w; acc[1][d] += x1 * w; acc[2][d] += x2 * w; acc[3][d] += x3 * w;
        }
    }
    #pragma unroll
    for (int k = 0; k < 4; ++k)
        #pragma unroll
        for (int d = 0; d < 16; ++d)
            hB[(es + 32 * k) * 65 + dg * 16 + d] = act(acc[k][d]);
    __syncthreads();

    // layer 2 -> g_h
    #pragma unroll
    for (int k = 0; k < 4; ++k)
        #pragma unroll
        for (int d = 0; d < 16; ++d) acc[k][d] = 0.f;
    #pragma unroll 8
    for (int u = 0; u < 64; ++u) {
        float x0 = hB[(es      ) * 65 + u];
        float x1 = hB[(es + 32) * 65 + u];
        float x2 = hB[(es + 64) * 65 + u];
        float x3 = hB[(es + 96) * 65 + u];
        #pragma unroll
        for (int d = 0; d < 16; ++d) {
            float w = sw2[u * 64 + dg * 16 + d];
            acc[0][d] += x0 * w; acc[1][d] += x1 * w; acc[2][d] += x2 * w; acc[3][d] += x3 * w;
        }
    }
    #pragma unroll
    for (int k = 0; k < 4; ++k) {
        int e = ebase + es + 32 * k;
        if (e < N_EDGES) {
            #pragma unroll
            for (int d = 0; d < 16; ++d)
                g_h[(size_t)e * 64 + dg * 16 + d] = act(acc[k][d]);
        }
    }
}

// ---------------------------------------------------------------------------
// Kernel 3: fused tpw + tensor product + output GEMMs. (R3 proven)
// 32 edges/CTA, 256 threads (warp w owns edges 4w..4w+3; lane cg owns cols 4cg..+3)
// out_v factorization: out_v[e,n,i] = sh1_i * (P@Wv_top)[e,n] + ((Q*vs_i)@Wv_bot)[e,n]
// NOTE: here ssv uses the SoA node layout [s|v0|v1|v2] to match g_node.
// ---------------------------------------------------------------------------
__global__ void __launch_bounds__(256) edge_kernel(
    const float* __restrict__ ea,     // edge_attrs (E,4)
    const int*   __restrict__ eidx,   // edge_index (2,E): sender first
    const float* __restrict__ w3,     // (64,512)
    const float* __restrict__ Wos,    // (256,128)
    const float* __restrict__ Wov,    // (256,128)
    float* __restrict__ out)
{
    extern __shared__ float sm[];
    float* ssv = sm;                  // 32*512 = 16384 (gathered, SoA)
    float* sA  = ssv + 16384;         // 32*256 = 8192 (mid_s, coef folded)
    float* sP  = sA + 8192;           // 32*128 = 4096
    float* sQ  = sP + 4096;           // 32*128 = 4096
    float* sh  = sQ + 4096;           // 32*64  = 2048
    float* sW  = sh + 2048;           // 64*128 = 8192 (B staging)
    float* sea = sW + 8192;           // 128
    int*   snd = (int*)(sea + 128);   // 32

    const float C0 = 0.70710678118654752f / 128.0f;                       // sqrt(.5)/(8*16)
    const float C3 = 0.70710678118654752f / (128.0f * 1.7320508075688772f);

    int t = threadIdx.x;
    int warp = t >> 5;
    int cg = t & 31;
    int ebase = blockIdx.x * 32;

    if (t < 32) snd[t] = eidx[ebase + t];
    if (t >= 128 && t < 256) sea[t - 128] = ea[ebase * 4 + (t - 128)];
    __syncthreads();

    { // gather node rows (32 x 512 floats, 8 threads/row, float4)
        int r = t >> 3, q = t & 7;
        const float4* src = (const float4*)g_node + (size_t)snd[r] * 128;
        float4* dst = (float4*)ssv + r * 128;
        #pragma unroll
        for (int j = 0; j < 16; ++j) dst[q + 8 * j] = src[q + 8 * j];
    }
    { // h tile (512 float4)
        const float4* src = (const float4*)g_h + (size_t)ebase * 16;
        float4* dst = (float4*)sh;
        dst[t] = src[t];
        dst[t + 256] = src[t + 256];
    }
    __syncthreads();

    int e0 = warp * 4;
    const float4* w34 = (const float4*)w3;
    float4* sW4 = (float4*)sW;

    // ---- tpw chunks -> A / P / Q (coefficients folded) ----
    for (int c = 0; c < 4; ++c) {
        #pragma unroll
        for (int j = 0; j < 8; ++j) {
            int idx = t + 256 * j;           // < 2048
            int u = idx >> 5, q = idx & 31;
            sW4[idx] = w34[u * 128 + c * 32 + q];
        }
        __syncthreads();

        float acc[4][4];
        #pragma unroll
        for (int k = 0; k < 4; ++k) { acc[k][0]=0.f; acc[k][1]=0.f; acc[k][2]=0.f; acc[k][3]=0.f; }
        #pragma unroll 4
        for (int u = 0; u < 64; ++u) {
            float4 b = sW4[u * 32 + cg];
            #pragma unroll
            for (int k = 0; k < 4; ++k) {
                float a = sh[(e0 + k) * 64 + u];
                acc[k][0] += a * b.x; acc[k][1] += a * b.y;
                acc[k][2] += a * b.z; acc[k][3] += a * b.w;
            }
        }
        #pragma unroll
        for (int k = 0; k < 4; ++k) {
            int e = e0 + k;
            float s0 = sea[e * 4];
            if (c == 0) {
                float4 sv = ((const float4*)(ssv + e * 512))[cg];
                float4 v;
                v.x = C0 * acc[k][0] * sv.x * s0; v.y = C0 * acc[k][1] * sv.y * s0;
                v.z = C0 * acc[k][2] * sv.z * s0; v.w = C0 * acc[k][3] * sv.w * s0;
                ((float4*)sA)[e * 64 + cg] = v;
            } else if (c == 1) {
                float4 sv = ((const float4*)(ssv + e * 512))[cg];
                float4 v;
                v.x = C0 * acc[k][0] * sv.x; v.y = C0 * acc[k][1] * sv.y;
                v.z = C0 * acc[k][2] * sv.z; v.w = C0 * acc[k][3] * sv.w;
                ((float4*)sP)[e * 32 + cg] = v;
            } else if (c == 2) {
                float4 v;
                v.x = C0 * acc[k][0] * s0; v.y = C0 * acc[k][1] * s0;
                v.z = C0 * acc[k][2] * s0; v.w = C0 * acc[k][3] * s0;
                ((float4*)sQ)[e * 32 + cg] = v;
            } else {
                float s1 = sea[e * 4 + 1], s2 = sea[e * 4 + 2], s3 = sea[e * 4 + 3];
                float4 v0 = ((const float4*)(ssv + e * 512 + 128))[cg];
                float4 v1 = ((const float4*)(ssv + e * 512 + 256))[cg];
                float4 v2 = ((const float4*)(ssv + e * 512 + 384))[cg];
                float4 v;
                v.x = C3 * acc[k][0] * (v0.x * s1 + v1.x * s2 + v2.x * s3);
                v.y = C3 * acc[k][1] * (v0.y * s1 + v1.y * s2 + v2.y * s3);
                v.z = C3 * acc[k][2] * (v0.z * s1 + v1.z * s2 + v2.z * s3);
                v.w = C3 * acc[k][3] * (v0.w * s1 + v1.w * s2 + v2.w * s3);
                ((float4*)sA)[e * 64 + 32 + cg] = v;
            }
        }
        __syncthreads();
    }

    // ---- out_s = A(32x256) @ Wos(256x128) ----
    {
        float accs[4][4];
        #pragma unroll
        for (int k = 0; k < 4; ++k) { accs[k][0]=0.f; accs[k][1]=0.f; accs[k][2]=0.f; accs[k][3]=0.f; }
        const float4* Ws4 = (const float4*)Wos;
        for (int kt = 0; kt < 4; ++kt) {
            #pragma unroll
            for (int j = 0; j < 8; ++j) { int idx = t + 256 * j; sW4[idx] = Ws4[kt * 2048 + idx]; }
            __syncthreads();
            #pragma unroll 4
            for (int u = 0; u < 64; ++u) {
                float4 b = sW4[u * 32 + cg];
                #pragma unroll
                for (int k = 0; k < 4; ++k) {
                    float a = sA[(e0 + k) * 256 + kt * 64 + u];
                    accs[k][0] += a * b.x; accs[k][1] += a * b.y;
                    accs[k][2] += a * b.z; accs[k][3] += a * b.w;
                }
            }
            __syncthreads();
        }
        #pragma unroll
        for (int k = 0; k < 4; ++k) {
            size_t e = (size_t)(ebase + e0 + k);
            ((float4*)out)[e * 128 + cg] =
                make_float4(accs[k][0], accs[k][1], accs[k][2], accs[k][3]);
        }
    }

    // ---- PV = P(32x128) @ Wv_top(128x128) ----
    float accp[4][4];
    #pragma unroll
    for (int k = 0; k < 4; ++k) { accp[k][0]=0.f; accp[k][1]=0.f; accp[k][2]=0.f; accp[k][3]=0.f; }
    const float4* Wv4 = (const float4*)Wov;
    for (int kt = 0; kt < 2; ++kt) {
        #pragma unroll
        for (int j = 0; j < 8; ++j) { int idx = t + 256 * j; sW4[idx] = Wv4[kt * 2048 + idx]; }
        __syncthreads();
        #pragma unroll 4
        for (int u = 0; u < 64; ++u) {
            float4 b = sW4[u * 32 + cg];
            #pragma unroll
            for (int k = 0; k < 4; ++k) {
                float a = sP[(e0 + k) * 128 + kt * 64 + u];
                accp[k][0] += a * b.x; accp[k][1] += a * b.y;
                accp[k][2] += a * b.z; accp[k][3] += a * b.w;
            }
        }
        __syncthreads();
    }

    // ---- QV_i = (Q*vs_i) @ Wv_bot (SoA v reads) ----
    float accq[3][4][4];
    #pragma unroll
    for (int i = 0; i < 3; ++i)
        #pragma unroll
        for (int k = 0; k < 4; ++k) { accq[i][k][0]=0.f; accq[i][k][1]=0.f; accq[i][k][2]=0.f; accq[i][k][3]=0.f; }
    for (int kt = 0; kt < 2; ++kt) {
        #pragma unroll
        for (int j = 0; j < 8; ++j) { int idx = t + 256 * j; sW4[idx] = Wv4[(128 + kt * 64) * 32 + idx]; }
        __syncthreads();
        #pragma unroll 2
        for (int u = 0; u < 64; ++u) {
            float4 b = sW4[u * 32 + cg];
            int uu = kt * 64 + u;
            #pragma unroll
            for (int k = 0; k < 4; ++k) {
                int e = e0 + k;
                float q = sQ[e * 128 + uu];
                float q0 = q * ssv[e * 512 + 128 + uu];
                float q1 = q * ssv[e * 512 + 256 + uu];
                float q2 = q * ssv[e * 512 + 384 + uu];
                accq[0][k][0] += q0 * b.x; accq[0][k][1] += q0 * b.y; accq[0][k][2] += q0 * b.z; accq[0][k][3] += q0 * b.w;
                accq[1][k][0] += q1 * b.x; accq[1][k][1] += q1 * b.y; accq[1][k][2] += q1 * b.z; accq[1][k][3] += q1 * b.w;
                accq[2][k][0] += q2 * b.x; accq[2][k][1] += q2 * b.y; accq[2][k][2] += q2 * b.z; accq[2][k][3] += q2 * b.w;
            }
        }
        __syncthreads();
    }

    // ---- combine + restage out_v through smem for coalesced stores ----
    float* vbuf = sA;   // sA(8192)+sP(4096) contiguous = 12288 floats = 32*384
    #pragma unroll
    for (int k = 0; k < 4; ++k) {
        int e = e0 + k;
        float s1 = sea[e * 4 + 1], s2 = sea[e * 4 + 2], s3 = sea[e * 4 + 3];
        #pragma unroll
        for (int j = 0; j < 4; ++j) {
            int n = cg * 4 + j;
            float pvv = accp[k][j];
            vbuf[e * 384 + n * 3 + 0] = s1 * pvv + accq[0][k][j];
            vbuf[e * 384 + n * 3 + 1] = s2 * pvv + accq[1][k][j];
            vbuf[e * 384 + n * 3 + 2] = s3 * pvv + accq[2][k][j];
        }
    }
    __syncthreads();
    float4* vb4 = (float4*)vbuf;
    #pragma unroll
    for (int j = 0; j < 12; ++j) {
        int idx = t + 256 * j;      // < 3072
        int e = idx / 96, rem = idx % 96;
        ((float4*)out)[(size_t)(ebase + e) * 128 + 32 + rem] = vb4[idx];
    }
}

// ---------------------------------------------------------------------------
extern "C" void kernel_launch(void* const* d_in, const int* in_sizes, int n_in,
                              void* d_out, int out_size) {
    const float* node_feats = (const float*)d_in[0];
    const float* edge_attrs = (const float*)d_in[1];
    const float* edge_feats = (const float*)d_in[2];
    const int*   edge_index = (const int*)d_in[3];
    const float* W_up_s  = (const float*)d_in[4];
    const float* W_up_v  = (const float*)d_in[5];
    const float* mlp_w0  = (const float*)d_in[6];
    const float* mlp_w1  = (const float*)d_in[7];
    const float* mlp_w2  = (const float*)d_in[8];
    const float* mlp_w3  = (const float*)d_in[9];
    const float* W_out_s = (const float*)d_in[10];
    const float* W_out_v = (const float*)d_in[11];
    float* out = (float*)d_out;

    size_t smem1 = (size_t)40960 * 4;   // 160 KB
    size_t smem2 = (size_t)26368 * 4;   // 103 KB
    size_t smem3 = (size_t)43200 * 4;   // 168.75 KB
    cudaFuncSetAttribute(node_kernel, cudaFuncAttributeMaxDynamicSharedMemorySize, (int)smem1);
    cudaFuncSetAttribute(mlp_kernel,  cudaFuncAttributeMaxDynamicSharedMemorySize, (int)smem2);
    cudaFuncSetAttribute(edge_kernel, cudaFuncAttributeMaxDynamicSharedMemorySize, (int)smem3);

    node_kernel<<<148, 512, smem1>>>(node_feats, W_up_s, W_up_v);
    mlp_kernel<<<(N_EDGES + 127) / 128, 128, smem2>>>(edge_feats, mlp_w0, mlp_w1, mlp_w2);
    edge_kernel<<<N_EDGES / 32, 256, smem3>>>(edge_attrs, edge_index, mlp_w3,
                                              W_out_s, W_out_v, out);
}